// round 6
// baseline (speedup 1.0000x reference)
#include <cuda_runtime.h>
#include <cuda_fp16.h>

// Problem constants
#define BB 8
#define CC 4
#define DD 128
#define HH 128
#define WW 128
#define FDIM 512
#define VOL (1<<21)          // 128^3

// Per-batch affine coefficients: integer (w,h,d) -> (ix,iy,iz)
__device__ float g_A[BB * 12];

// Scratch (x-pair layout): slot s = {c0..c3 @ x=s, c0..c3 @ x=s+1} as 8 fp16 = 16B.
__device__ uint4 g_scr[(size_t)BB * VOL];

static __device__ __forceinline__ unsigned pack2(float a, float b) {
    __half2 h = __floats2half2_rn(a, b);
    return *reinterpret_cast<unsigned*>(&h);
}

// Packed f32x2 ops (Blackwell)
#define MUL_F32X2(out, a, b) \
    asm("mul.rn.f32x2 %0, %1, %2;" : "=l"(out) : "l"(a), "l"(b))
#define FMA_F32X2(d, a, b, c) \
    asm("fma.rn.f32x2 %0, %1, %2, %3;" : "=l"(d) : "l"(a), "l"(b), "l"(c))
#define PACK_F32X2(out, lo, hi) \
    asm("mov.b64 %0, {%1, %2};" : "=l"(out) : "f"(lo), "f"(hi))
#define UNPACK_F32X2(lo, hi, in) \
    asm("mov.b64 {%0, %1}, %2;" : "=f"(lo), "=f"(hi) : "l"(in))

// ---------------------------------------------------------------------------
// rot: per-batch GEMV -> affine coefficients. 1 block, warp per batch.
// ---------------------------------------------------------------------------
__global__ void rot_kernel(const float* __restrict__ im_feat,
                           const float* __restrict__ pos_w,
                           const float* __restrict__ pos_b) {
    const int wid = threadIdx.x >> 5;
    const int lane = threadIdx.x & 31;
    if (wid >= BB) return;
    float pm = 0.f, pr = 0.f;
    for (int j = lane; j < FDIM; j += 32) {
        float f = im_feat[wid * FDIM + j];
        pm = fmaf(f, pos_w[j], pm);
        pr = fmaf(f, pos_w[FDIM + j], pr);
    }
    #pragma unroll
    for (int s = 16; s; s >>= 1) {
        pm += __shfl_xor_sync(0xffffffffu, pm, s);
        pr += __shfl_xor_sync(0xffffffffu, pr, s);
    }
    if (lane == 0) {
        float mu  = pm + pos_b[0];
        float rho = pr + pos_b[1];
        float cm = cosf(mu),  sm = sinf(mu);
        float cr = cosf(rho), sr = sinf(rho);
        const float SC = 128.0f / 127.0f;
        float* A = &g_A[wid * 12];
        float r0 = cm, r1 = sm * sr, r2 = -sm * cr;
        float r4 = cr, r5 = sr;
        float r6 = sm, r7 = -cm * sr, r8 = cm * cr;
        A[0] = r0 * SC;  A[1] = r1 * SC;  A[2] = r2 * SC;
        A[3] = 64.0f * (1.0f - (r0 + r1 + r2)) - 0.5f;
        A[4] = r4 * SC;  A[5] = r5 * SC;
        A[6] = 64.0f * (1.0f - (r4 + r5)) - 0.5f;
        A[7] = 0.0f;
        A[8] = r6 * SC;  A[9] = r7 * SC;  A[10] = r8 * SC;
        A[11] = 64.0f * (1.0f - (r6 + r7 + r8)) - 0.5f;
    }
}

// ---------------------------------------------------------------------------
// prep_b: batch b of [B,C,D,H,W] fp32 -> fp16 x-pair channels-last scratch.
// Thread handles 4 consecutive voxels; neighbor (x+4) column via warp shuffle.
// grid = VOL/4/256 = 2048 blocks.
// ---------------------------------------------------------------------------
__global__ void __launch_bounds__(256)
prep_kernel(const float* __restrict__ x, int b) {
    const unsigned t = blockIdx.x * 256 + threadIdx.x;   // < VOL/4
    const unsigned s = t << 2;                           // first voxel in batch
    const float* base = x + ((size_t)b << 23);           // b*C*VOL

    float4 v0 = *(const float4*)(base + s);
    float4 v1 = *(const float4*)(base + VOL + s);
    float4 v2 = *(const float4*)(base + 2u * VOL + s);
    float4 v3 = *(const float4*)(base + 3u * VOL + s);

    // voxel s+4 value per channel: next lane's .x (lane 31 reloads)
    float n0 = __shfl_down_sync(0xffffffffu, v0.x, 1);
    float n1 = __shfl_down_sync(0xffffffffu, v1.x, 1);
    float n2 = __shfl_down_sync(0xffffffffu, v2.x, 1);
    float n3 = __shfl_down_sync(0xffffffffu, v3.x, 1);
    if ((threadIdx.x & 31) == 31) {
        unsigned sn = s + 4; if (sn >= VOL) sn = VOL - 1;   // value unused (w=127 -> weight 0)
        n0 = base[sn];
        n1 = base[VOL + sn];
        n2 = base[2u * VOL + sn];
        n3 = base[3u * VOL + sn];
    }

    float a0[5] = {v0.x, v0.y, v0.z, v0.w, n0};
    float a1[5] = {v1.x, v1.y, v1.z, v1.w, n1};
    float a2[5] = {v2.x, v2.y, v2.z, v2.w, n2};
    float a3[5] = {v3.x, v3.y, v3.z, v3.w, n3};

    uint4* dst = g_scr + (((size_t)b << 21) + s);
    #pragma unroll
    for (int j = 0; j < 4; ++j) {
        uint4 slot;
        slot.x = pack2(a0[j],     a1[j]);
        slot.y = pack2(a2[j],     a3[j]);
        slot.z = pack2(a0[j + 1], a1[j + 1]);
        slot.w = pack2(a2[j + 1], a3[j + 1]);
        dst[j] = slot;
    }
}

// ---------------------------------------------------------------------------
// sample_b: rotated trilinear grid_sample for batch b. 4 LDG.128 per voxel
// (x-pair x 4 channels per load). f32x2 packed lerp math.
// grid = VOL/256 = 8192 blocks.
// ---------------------------------------------------------------------------
__global__ void __launch_bounds__(256)
sample_kernel(float* __restrict__ out, int b) {
    __shared__ float A[12];
    if (threadIdx.x < 12) A[threadIdx.x] = g_A[b * 12 + threadIdx.x];
    __syncthreads();

    const unsigned tid = blockIdx.x * 256 + threadIdx.x;   // < VOL
    const int w = tid & (WW - 1);
    const int h = (tid >> 7) & (HH - 1);
    const int d = tid >> 14;
    const float fw = (float)w, fh = (float)h, fd = (float)d;

    const float ix = fmaf(A[0], fw, fmaf(A[1], fh, fmaf(A[2],  fd, A[3])));
    const float iy =               fmaf(A[4], fh, fmaf(A[5],  fd, A[6]));
    const float iz = fmaf(A[8], fw, fmaf(A[9], fh, fmaf(A[10], fd, A[11])));

    const float fxf = floorf(ix), fyf = floorf(iy), fzf = floorf(iz);
    const int ix0 = (int)fxf, iy0 = (int)fyf, iz0 = (int)fzf;
    const float fx = ix - fxf, fy = iy - fyf, fz = iz - fzf;

    float wAv, wBv, wy0, wy1, wz0, wz1;
    int xs, y0c, y1c, z0c, z1c;

    const bool interior = (ix0 >= 0) & (ix0 < WW - 1) &
                          (iy0 >= 0) & (iy0 < HH - 1) &
                          (iz0 >= 0) & (iz0 < DD - 1);

    if (__all_sync(0xffffffffu, interior)) {
        wAv = 1.0f - fx; wBv = fx;
        wy0 = 1.0f - fy; wy1 = fy;
        wz0 = 1.0f - fz; wz1 = fz;
        xs = ix0; y0c = iy0; y1c = iy0 + 1; z0c = iz0; z1c = iz0 + 1;
    } else {
        const int x1 = ix0 + 1, y1 = iy0 + 1, z1 = iz0 + 1;
        const float wx0 = (ix0 >= 0 && ix0 < WW) ? (1.0f - fx) : 0.0f;
        const float wx1 = (x1  >= 0 && x1  < WW) ? fx          : 0.0f;
        wy0 = (iy0 >= 0 && iy0 < HH) ? (1.0f - fy) : 0.0f;
        wy1 = (y1  >= 0 && y1  < HH) ? fy          : 0.0f;
        wz0 = (iz0 >= 0 && iz0 < DD) ? (1.0f - fz) : 0.0f;
        wz1 = (z1  >= 0 && z1  < DD) ? fz          : 0.0f;
        xs  = min(max(ix0, 0), WW - 1);
        wAv = (ix0 >= 0) ? wx0 : wx1;
        wBv = (ix0 >= 0) ? wx1 : 0.0f;
        y0c = min(max(iy0, 0), HH - 1);
        y1c = min(max(y1,  0), HH - 1);
        z0c = min(max(iz0, 0), DD - 1);
        z1c = min(max(z1,  0), DD - 1);
    }

    const int zb0 = z0c << 14, zb1 = z1c << 14;
    const int yb0 = y0c << 7,  yb1 = y1c << 7;

    const uint4* p = g_scr + ((size_t)b << 21);

    const uint4 g00 = __ldg(p + (zb0 + yb0 + xs));
    const uint4 g01 = __ldg(p + (zb0 + yb1 + xs));
    const uint4 g10 = __ldg(p + (zb1 + yb0 + xs));
    const uint4 g11 = __ldg(p + (zb1 + yb1 + xs));

    const float c00 = wz0 * wy0;
    const float c01 = wz0 * wy1;
    const float c10 = wz1 * wy0;
    const float c11 = wz1 * wy1;

    unsigned long long WA, WB, acc01, acc23;
    PACK_F32X2(WA, wAv, wAv);
    PACK_F32X2(WB, wBv, wBv);
    {
        float zf = 0.0f;
        PACK_F32X2(acc01, zf, zf);
        acc23 = acc01;
    }

    #define COLUMN(g, cwf)                                                     \
    {                                                                          \
        float2 lo01 = __half22float2(*reinterpret_cast<const __half2*>(&g.x)); \
        float2 lo23 = __half22float2(*reinterpret_cast<const __half2*>(&g.y)); \
        float2 hi01 = __half22float2(*reinterpret_cast<const __half2*>(&g.z)); \
        float2 hi23 = __half22float2(*reinterpret_cast<const __half2*>(&g.w)); \
        unsigned long long L01, L23, H01, H23, CW, m0, m1, t01, t23;           \
        PACK_F32X2(L01, lo01.x, lo01.y);                                       \
        PACK_F32X2(L23, lo23.x, lo23.y);                                       \
        PACK_F32X2(H01, hi01.x, hi01.y);                                       \
        PACK_F32X2(H23, hi23.x, hi23.y);                                       \
        PACK_F32X2(CW, cwf, cwf);                                              \
        MUL_F32X2(m0, WB, H01);                                                \
        FMA_F32X2(t01, WA, L01, m0);                                           \
        MUL_F32X2(m1, WB, H23);                                                \
        FMA_F32X2(t23, WA, L23, m1);                                           \
        FMA_F32X2(acc01, CW, t01, acc01);                                      \
        FMA_F32X2(acc23, CW, t23, acc23);                                      \
    }

    COLUMN(g00, c00)
    COLUMN(g01, c01)
    COLUMN(g10, c10)
    COLUMN(g11, c11)

    float r0, r1, r2, r3;
    UNPACK_F32X2(r0, r1, acc01);
    UNPACK_F32X2(r2, r3, acc23);

    const unsigned base = ((unsigned)b << 23) + tid;   // b*C*VOL + tid
    out[base]              = r0;
    out[base + (1u << 21)] = r1;
    out[base + (2u << 21)] = r2;
    out[base + (3u << 21)] = r3;
}

// ---------------------------------------------------------------------------
// Host side: fork-join pipeline. prep (stream s1) overlaps sample (stream s2);
// sample_b waits on event eP[b]. All capture-legal (events + stream waits).
// Streams/events created once in a static initializer (no device allocation).
// ---------------------------------------------------------------------------
static cudaStream_t g_s1, g_s2;
static cudaEvent_t g_eRoot, g_eP[BB], g_eS;
namespace {
struct PipeInit {
    PipeInit() {
        cudaStreamCreateWithFlags(&g_s1, cudaStreamNonBlocking);
        cudaStreamCreateWithFlags(&g_s2, cudaStreamNonBlocking);
        cudaEventCreateWithFlags(&g_eRoot, cudaEventDisableTiming);
        for (int i = 0; i < BB; ++i)
            cudaEventCreateWithFlags(&g_eP[i], cudaEventDisableTiming);
        cudaEventCreateWithFlags(&g_eS, cudaEventDisableTiming);
    }
};
static PipeInit g_pipe_init;
}

extern "C" void kernel_launch(void* const* d_in, const int* in_sizes, int n_in,
                              void* d_out, int out_size) {
    const float* x       = (const float*)d_in[0];
    const float* im_feat = (const float*)d_in[1];
    const float* pos_w   = (const float*)d_in[2];
    const float* pos_b   = (const float*)d_in[3];
    float* out = (float*)d_out;

    // Fork from the (captured) default stream
    cudaEventRecord(g_eRoot, 0);
    cudaStreamWaitEvent(g_s1, g_eRoot, 0);
    cudaStreamWaitEvent(g_s2, g_eRoot, 0);

    rot_kernel<<<1, 256, 0, g_s1>>>(im_feat, pos_w, pos_b);
    for (int b = 0; b < BB; ++b) {
        prep_kernel<<<VOL / 4 / 256, 256, 0, g_s1>>>(x, b);
        cudaEventRecord(g_eP[b], g_s1);
        cudaStreamWaitEvent(g_s2, g_eP[b], 0);
        sample_kernel<<<VOL / 256, 256, 0, g_s2>>>(out, b);
    }

    // Join back into the default stream
    cudaEventRecord(g_eS, g_s2);
    cudaStreamWaitEvent(0, g_eS, 0);
}

// round 7
// speedup vs baseline: 1.1316x; 1.1316x over previous
#include <cuda_runtime.h>
#include <cuda_fp16.h>

// Problem constants
#define BB 8
#define CC 4
#define DD 128
#define HH 128
#define WW 128
#define FDIM 512
#define VOL (1<<21)          // 128^3

// Per-batch affine coefficients: integer (w,h,d) -> (ix,iy,iz)
__device__ float g_A[BB * 12];

// Scratch (x-pair layout): slot s = {c0..c3 @ x=s, c0..c3 @ x=s+1} as 8 fp16 = 16B.
__device__ uint4 g_scr[(size_t)BB * VOL];

static __device__ __forceinline__ unsigned pack2(float a, float b) {
    __half2 h = __floats2half2_rn(a, b);
    return *reinterpret_cast<unsigned*>(&h);
}

// Packed f32x2 ops (Blackwell)
#define MUL_F32X2(out, a, b) \
    asm("mul.rn.f32x2 %0, %1, %2;" : "=l"(out) : "l"(a), "l"(b))
#define FMA_F32X2(d, a, b, c) \
    asm("fma.rn.f32x2 %0, %1, %2, %3;" : "=l"(d) : "l"(a), "l"(b), "l"(c))
#define PACK_F32X2(out, lo, hi) \
    asm("mov.b64 %0, {%1, %2};" : "=l"(out) : "f"(lo), "f"(hi))
#define UNPACK_F32X2(lo, hi, in) \
    asm("mov.b64 {%0, %1}, %2;" : "=f"(lo), "=f"(hi) : "l"(in))

// ---------------------------------------------------------------------------
// Kernel 1: prep (monolithic, all batches). Block 0 computes the per-batch
// affine coefficients. All blocks transpose [B,C,D,H,W] fp32 into the fp16
// x-pair channels-last scratch. Thread handles 4 consecutive voxels.
// ---------------------------------------------------------------------------
__global__ void __launch_bounds__(256)
prep_kernel(const float* __restrict__ x,
            const float* __restrict__ im_feat,
            const float* __restrict__ pos_w,
            const float* __restrict__ pos_b) {
    if (blockIdx.x == 0) {
        const int wid = threadIdx.x >> 5;
        const int lane = threadIdx.x & 31;
        if (wid < BB) {
            float pm = 0.f, pr = 0.f;
            for (int j = lane; j < FDIM; j += 32) {
                float f = im_feat[wid * FDIM + j];
                pm = fmaf(f, pos_w[j], pm);
                pr = fmaf(f, pos_w[FDIM + j], pr);
            }
            #pragma unroll
            for (int s = 16; s; s >>= 1) {
                pm += __shfl_xor_sync(0xffffffffu, pm, s);
                pr += __shfl_xor_sync(0xffffffffu, pr, s);
            }
            if (lane == 0) {
                float mu  = pm + pos_b[0];
                float rho = pr + pos_b[1];
                float cm = cosf(mu),  sm = sinf(mu);
                float cr = cosf(rho), sr = sinf(rho);
                const float SC = 128.0f / 127.0f;
                float* A = &g_A[wid * 12];
                float r0 = cm, r1 = sm * sr, r2 = -sm * cr;
                float r4 = cr, r5 = sr;
                float r6 = sm, r7 = -cm * sr, r8 = cm * cr;
                A[0] = r0 * SC;  A[1] = r1 * SC;  A[2] = r2 * SC;
                A[3] = 64.0f * (1.0f - (r0 + r1 + r2)) - 0.5f;
                A[4] = r4 * SC;  A[5] = r5 * SC;
                A[6] = 64.0f * (1.0f - (r4 + r5)) - 0.5f;
                A[7] = 0.0f;
                A[8] = r6 * SC;  A[9] = r7 * SC;  A[10] = r8 * SC;
                A[11] = 64.0f * (1.0f - (r6 + r7 + r8)) - 0.5f;
            }
        }
    }

    const size_t t = (size_t)blockIdx.x * 256 + threadIdx.x;  // < B*VOL/4
    const size_t s4 = t << 2;                                 // first voxel
    const size_t b = s4 >> 21;
    const unsigned s = (unsigned)(s4 & (VOL - 1));
    const float* base = x + (b << 23);                        // b*C*VOL

    float4 v0 = *(const float4*)(base + s);
    float4 v1 = *(const float4*)(base + VOL + s);
    float4 v2 = *(const float4*)(base + 2u * VOL + s);
    float4 v3 = *(const float4*)(base + 3u * VOL + s);
    unsigned sn = s + 4; if (sn >= VOL) sn = VOL - 1;  // value unused (weight 0)
    float a0[5] = {v0.x, v0.y, v0.z, v0.w, base[sn]};
    float a1[5] = {v1.x, v1.y, v1.z, v1.w, base[VOL + sn]};
    float a2[5] = {v2.x, v2.y, v2.z, v2.w, base[2u * VOL + sn]};
    float a3[5] = {v3.x, v3.y, v3.z, v3.w, base[3u * VOL + sn]};

    uint4* dst = g_scr + s4;
    #pragma unroll
    for (int j = 0; j < 4; ++j) {
        uint4 slot;
        slot.x = pack2(a0[j],     a1[j]);
        slot.y = pack2(a2[j],     a3[j]);
        slot.z = pack2(a0[j + 1], a1[j + 1]);
        slot.w = pack2(a2[j + 1], a3[j + 1]);
        dst[j] = slot;
    }
}

// ---------------------------------------------------------------------------
// Kernel 2: rotated trilinear grid_sample. 2 voxels per thread (d and d+64)
// => 8 independent LDG.128 in flight; f32x2 packed lerp math.
// grid = (VOL/2/256, B), block 256.
// ---------------------------------------------------------------------------

// Per-voxel index/weight setup: defines wA_, wB_, c00_..c11_, o00_..o11_.
#define SETUP(sfx, ixv, iyv, izv)                                              \
    float wA##sfx, wB##sfx, c00##sfx, c01##sfx, c10##sfx, c11##sfx;            \
    int o00##sfx, o01##sfx, o10##sfx, o11##sfx;                                \
    {                                                                          \
        const float fxf = floorf(ixv), fyf = floorf(iyv), fzf = floorf(izv);   \
        const int ix0 = (int)fxf, iy0 = (int)fyf, iz0 = (int)fzf;              \
        const float fx = ixv - fxf, fy = iyv - fyf, fz = izv - fzf;            \
        float wy0, wy1, wz0, wz1; int xs, y0c, y1c, z0c, z1c;                  \
        const bool interior = (ix0 >= 0) & (ix0 < WW - 1) &                    \
                              (iy0 >= 0) & (iy0 < HH - 1) &                    \
                              (iz0 >= 0) & (iz0 < DD - 1);                     \
        if (__all_sync(0xffffffffu, interior)) {                               \
            wA##sfx = 1.0f - fx; wB##sfx = fx;                                 \
            wy0 = 1.0f - fy; wy1 = fy; wz0 = 1.0f - fz; wz1 = fz;              \
            xs = ix0; y0c = iy0; y1c = iy0 + 1; z0c = iz0; z1c = iz0 + 1;      \
        } else {                                                               \
            const int x1 = ix0 + 1, y1 = iy0 + 1, z1 = iz0 + 1;                \
            const float wx0 = (ix0 >= 0 && ix0 < WW) ? (1.0f - fx) : 0.0f;     \
            const float wx1 = (x1  >= 0 && x1  < WW) ? fx          : 0.0f;     \
            wy0 = (iy0 >= 0 && iy0 < HH) ? (1.0f - fy) : 0.0f;                 \
            wy1 = (y1  >= 0 && y1  < HH) ? fy          : 0.0f;                 \
            wz0 = (iz0 >= 0 && iz0 < DD) ? (1.0f - fz) : 0.0f;                 \
            wz1 = (z1  >= 0 && z1  < DD) ? fz          : 0.0f;                 \
            xs  = min(max(ix0, 0), WW - 1);                                    \
            wA##sfx = (ix0 >= 0) ? wx0 : wx1;                                  \
            wB##sfx = (ix0 >= 0) ? wx1 : 0.0f;                                 \
            y0c = min(max(iy0, 0), HH - 1);                                    \
            y1c = min(max(y1,  0), HH - 1);                                    \
            z0c = min(max(iz0, 0), DD - 1);                                    \
            z1c = min(max(z1,  0), DD - 1);                                    \
        }                                                                      \
        const int zb0 = z0c << 14, zb1 = z1c << 14;                            \
        const int yb0 = y0c << 7,  yb1 = y1c << 7;                             \
        o00##sfx = zb0 + yb0 + xs;                                             \
        o01##sfx = zb0 + yb1 + xs;                                             \
        o10##sfx = zb1 + yb0 + xs;                                             \
        o11##sfx = zb1 + yb1 + xs;                                             \
        c00##sfx = wz0 * wy0; c01##sfx = wz0 * wy1;                            \
        c10##sfx = wz1 * wy0; c11##sfx = wz1 * wy1;                            \
    }

// Accumulate one corner column (x-pair x 4ch) with packed f32x2 math.
#define COLUMN(g, cwf, WAp, WBp, acc01, acc23)                                 \
    {                                                                          \
        float2 lo01 = __half22float2(*reinterpret_cast<const __half2*>(&g.x)); \
        float2 lo23 = __half22float2(*reinterpret_cast<const __half2*>(&g.y)); \
        float2 hi01 = __half22float2(*reinterpret_cast<const __half2*>(&g.z)); \
        float2 hi23 = __half22float2(*reinterpret_cast<const __half2*>(&g.w)); \
        unsigned long long L01, L23, H01, H23, CW, m0, m1, t01, t23;           \
        PACK_F32X2(L01, lo01.x, lo01.y);                                       \
        PACK_F32X2(L23, lo23.x, lo23.y);                                       \
        PACK_F32X2(H01, hi01.x, hi01.y);                                       \
        PACK_F32X2(H23, hi23.x, hi23.y);                                       \
        PACK_F32X2(CW, cwf, cwf);                                              \
        MUL_F32X2(m0, WBp, H01);                                               \
        FMA_F32X2(t01, WAp, L01, m0);                                          \
        MUL_F32X2(m1, WBp, H23);                                               \
        FMA_F32X2(t23, WAp, L23, m1);                                          \
        FMA_F32X2(acc01, CW, t01, acc01);                                      \
        FMA_F32X2(acc23, CW, t23, acc23);                                      \
    }

__global__ void __launch_bounds__(256, 4)
sample_kernel(float* __restrict__ out) {
    const int b = blockIdx.y;

    __shared__ float A[12];
    if (threadIdx.x < 12) A[threadIdx.x] = g_A[b * 12 + threadIdx.x];
    __syncthreads();

    const unsigned tid = blockIdx.x * 256 + threadIdx.x;   // < VOL/2
    const int w = tid & (WW - 1);
    const int h = (tid >> 7) & (HH - 1);
    const int d = tid >> 14;                                // 0..63
    const float fw = (float)w, fh = (float)h, fd = (float)d;

    // voxel a: (w, h, d); voxel b: (w, h, d+64)
    const float ixa = fmaf(A[0], fw, fmaf(A[1], fh, fmaf(A[2],  fd, A[3])));
    const float iya =               fmaf(A[4], fh, fmaf(A[5],  fd, A[6]));
    const float iza = fmaf(A[8], fw, fmaf(A[9], fh, fmaf(A[10], fd, A[11])));
    const float ixb = fmaf(64.0f, A[2],  ixa);
    const float iyb = fmaf(64.0f, A[5],  iya);
    const float izb = fmaf(64.0f, A[10], iza);

    SETUP(a, ixa, iya, iza)
    SETUP(b, ixb, iyb, izb)

    const uint4* p = g_scr + ((size_t)b << 21 ? 0 : 0) + ((size_t)blockIdx.y << 21);

    // Issue all 8 gathers before any math (MLP=8 per thread).
    const uint4 ga00 = __ldg(p + o00a);
    const uint4 ga01 = __ldg(p + o01a);
    const uint4 ga10 = __ldg(p + o10a);
    const uint4 ga11 = __ldg(p + o11a);
    const uint4 gb00 = __ldg(p + o00b);
    const uint4 gb01 = __ldg(p + o01b);
    const uint4 gb10 = __ldg(p + o10b);
    const uint4 gb11 = __ldg(p + o11b);

    unsigned long long WAa, WBa, WAb, WBb, acc01a, acc23a, acc01b, acc23b;
    PACK_F32X2(WAa, wAa, wAa);
    PACK_F32X2(WBa, wBa, wBa);
    PACK_F32X2(WAb, wAb, wAb);
    PACK_F32X2(WBb, wBb, wBb);
    {
        float zf = 0.0f;
        PACK_F32X2(acc01a, zf, zf);
        acc23a = acc01a; acc01b = acc01a; acc23b = acc01a;
    }

    COLUMN(ga00, c00a, WAa, WBa, acc01a, acc23a)
    COLUMN(ga01, c01a, WAa, WBa, acc01a, acc23a)
    COLUMN(ga10, c10a, WAa, WBa, acc01a, acc23a)
    COLUMN(ga11, c11a, WAa, WBa, acc01a, acc23a)
    COLUMN(gb00, c00b, WAb, WBb, acc01b, acc23b)
    COLUMN(gb01, c01b, WAb, WBb, acc01b, acc23b)
    COLUMN(gb10, c10b, WAb, WBb, acc01b, acc23b)
    COLUMN(gb11, c11b, WAb, WBb, acc01b, acc23b)

    float r0, r1, r2, r3, s0, s1, s2, s3;
    UNPACK_F32X2(r0, r1, acc01a);
    UNPACK_F32X2(r2, r3, acc23a);
    UNPACK_F32X2(s0, s1, acc01b);
    UNPACK_F32X2(s2, s3, acc23b);

    const unsigned basea = ((unsigned)b << 23) + tid;        // b*C*VOL + tid
    const unsigned baseb = basea + (1u << 20);               // voxel at d+64
    out[basea]              = r0;
    out[basea + (1u << 21)] = r1;
    out[basea + (2u << 21)] = r2;
    out[basea + (3u << 21)] = r3;
    out[baseb]              = s0;
    out[baseb + (1u << 21)] = s1;
    out[baseb + (2u << 21)] = s2;
    out[baseb + (3u << 21)] = s3;
}

extern "C" void kernel_launch(void* const* d_in, const int* in_sizes, int n_in,
                              void* d_out, int out_size) {
    const float* x       = (const float*)d_in[0];
    const float* im_feat = (const float*)d_in[1];
    const float* pos_w   = (const float*)d_in[2];
    const float* pos_b   = (const float*)d_in[3];
    float* out = (float*)d_out;

    prep_kernel<<<BB * VOL / 4 / 256, 256>>>(x, im_feat, pos_w, pos_b);
    dim3 grid(VOL / 2 / 256, BB);
    sample_kernel<<<grid, 256>>>(out);
}

// round 8
// speedup vs baseline: 1.1986x; 1.0592x over previous
#include <cuda_runtime.h>
#include <cuda_fp16.h>

// Problem constants
#define BB 8
#define CC 4
#define DD 128
#define HH 128
#define WW 128
#define FDIM 512
#define VOL (1<<21)          // 128^3

// Per-batch affine coefficients: integer (w,h,d) -> (ix,iy,iz)
__device__ float g_A[BB * 12];

// Scratch (x-pair layout): slot s = {c0..c3 @ x=s, c0..c3 @ x=s+1} as 8 fp16 = 16B.
__device__ uint4 g_scr[(size_t)BB * VOL];

static __device__ __forceinline__ unsigned pack2(float a, float b) {
    __half2 h = __floats2half2_rn(a, b);
    return *reinterpret_cast<unsigned*>(&h);
}

// Packed f32x2 ops (Blackwell)
#define MUL_F32X2(out, a, b) \
    asm("mul.rn.f32x2 %0, %1, %2;" : "=l"(out) : "l"(a), "l"(b))
#define FMA_F32X2(d, a, b, c) \
    asm("fma.rn.f32x2 %0, %1, %2, %3;" : "=l"(d) : "l"(a), "l"(b), "l"(c))
#define PACK_F32X2(out, lo, hi) \
    asm("mov.b64 %0, {%1, %2};" : "=l"(out) : "f"(lo), "f"(hi))
#define UNPACK_F32X2(lo, hi, in) \
    asm("mov.b64 {%0, %1}, %2;" : "=f"(lo), "=f"(hi) : "l"(in))

// ---------------------------------------------------------------------------
// Kernel 1: prep (monolithic). Block 0 also computes per-batch affine
// coefficients. Transposes [B,C,D,H,W] fp32 -> fp16 x-pair channels-last
// scratch. Thread handles 4 consecutive voxels; the x+4 neighbor column
// comes from the next lane via shuffle (lane 31 reloads).
// ---------------------------------------------------------------------------
__global__ void __launch_bounds__(256)
prep_kernel(const float* __restrict__ x,
            const float* __restrict__ im_feat,
            const float* __restrict__ pos_w,
            const float* __restrict__ pos_b) {
    if (blockIdx.x == 0) {
        const int wid = threadIdx.x >> 5;
        const int lane = threadIdx.x & 31;
        if (wid < BB) {
            float pm = 0.f, pr = 0.f;
            for (int j = lane; j < FDIM; j += 32) {
                float f = im_feat[wid * FDIM + j];
                pm = fmaf(f, pos_w[j], pm);
                pr = fmaf(f, pos_w[FDIM + j], pr);
            }
            #pragma unroll
            for (int s = 16; s; s >>= 1) {
                pm += __shfl_xor_sync(0xffffffffu, pm, s);
                pr += __shfl_xor_sync(0xffffffffu, pr, s);
            }
            if (lane == 0) {
                float mu  = pm + pos_b[0];
                float rho = pr + pos_b[1];
                float cm = cosf(mu),  sm = sinf(mu);
                float cr = cosf(rho), sr = sinf(rho);
                const float SC = 128.0f / 127.0f;
                float* A = &g_A[wid * 12];
                float r0 = cm, r1 = sm * sr, r2 = -sm * cr;
                float r4 = cr, r5 = sr;
                float r6 = sm, r7 = -cm * sr, r8 = cm * cr;
                A[0] = r0 * SC;  A[1] = r1 * SC;  A[2] = r2 * SC;
                A[3] = 64.0f * (1.0f - (r0 + r1 + r2)) - 0.5f;
                A[4] = r4 * SC;  A[5] = r5 * SC;
                A[6] = 64.0f * (1.0f - (r4 + r5)) - 0.5f;
                A[7] = 0.0f;
                A[8] = r6 * SC;  A[9] = r7 * SC;  A[10] = r8 * SC;
                A[11] = 64.0f * (1.0f - (r6 + r7 + r8)) - 0.5f;
            }
        }
    }

    const size_t t = (size_t)blockIdx.x * 256 + threadIdx.x;  // < B*VOL/4
    const size_t s4 = t << 2;                                 // first voxel
    const size_t b = s4 >> 21;
    const unsigned s = (unsigned)(s4 & (VOL - 1));
    const float* base = x + (b << 23);                        // b*C*VOL

    float4 v0 = *(const float4*)(base + s);
    float4 v1 = *(const float4*)(base + VOL + s);
    float4 v2 = *(const float4*)(base + 2u * VOL + s);
    float4 v3 = *(const float4*)(base + 3u * VOL + s);

    // voxel s+4 per channel = next lane's .x (lane 31 reloads; clamped value
    // is only ever paired with weight 0 at w=127 / row end)
    float n0 = __shfl_down_sync(0xffffffffu, v0.x, 1);
    float n1 = __shfl_down_sync(0xffffffffu, v1.x, 1);
    float n2 = __shfl_down_sync(0xffffffffu, v2.x, 1);
    float n3 = __shfl_down_sync(0xffffffffu, v3.x, 1);
    if ((threadIdx.x & 31) == 31) {
        unsigned sn = s + 4; if (sn >= VOL) sn = VOL - 1;
        n0 = base[sn];
        n1 = base[VOL + sn];
        n2 = base[2u * VOL + sn];
        n3 = base[3u * VOL + sn];
    }

    float a0[5] = {v0.x, v0.y, v0.z, v0.w, n0};
    float a1[5] = {v1.x, v1.y, v1.z, v1.w, n1};
    float a2[5] = {v2.x, v2.y, v2.z, v2.w, n2};
    float a3[5] = {v3.x, v3.y, v3.z, v3.w, n3};

    uint4* dst = g_scr + s4;
    #pragma unroll
    for (int j = 0; j < 4; ++j) {
        uint4 slot;
        slot.x = pack2(a0[j],     a1[j]);
        slot.y = pack2(a2[j],     a3[j]);
        slot.z = pack2(a0[j + 1], a1[j + 1]);
        slot.w = pack2(a2[j + 1], a3[j + 1]);
        dst[j] = slot;
    }
}

// ---------------------------------------------------------------------------
// Kernel 2: rotated trilinear grid_sample. 1 voxel/thread, 4 LDG.128,
// f32x2 packed lerps, interior fast path. Forced 8 blocks/SM (occ 100%).
// grid = (VOL/256, B), block 256.
// ---------------------------------------------------------------------------
__global__ void __launch_bounds__(256, 8)
sample_kernel(float* __restrict__ out) {
    const int b = blockIdx.y;

    __shared__ float A[12];
    if (threadIdx.x < 12) A[threadIdx.x] = g_A[b * 12 + threadIdx.x];
    __syncthreads();

    const unsigned tid = blockIdx.x * 256 + threadIdx.x;   // < VOL
    const int w = tid & (WW - 1);
    const int h = (tid >> 7) & (HH - 1);
    const int d = tid >> 14;
    const float fw = (float)w, fh = (float)h, fd = (float)d;

    const float ix = fmaf(A[0], fw, fmaf(A[1], fh, fmaf(A[2],  fd, A[3])));
    const float iy =               fmaf(A[4], fh, fmaf(A[5],  fd, A[6]));
    const float iz = fmaf(A[8], fw, fmaf(A[9], fh, fmaf(A[10], fd, A[11])));

    const float fxf = floorf(ix), fyf = floorf(iy), fzf = floorf(iz);
    const int ix0 = (int)fxf, iy0 = (int)fyf, iz0 = (int)fzf;
    const float fx = ix - fxf, fy = iy - fyf, fz = iz - fzf;

    float wAv, wBv, wy0, wy1, wz0, wz1;
    int xs, y0c, y1c, z0c, z1c;

    const bool interior = (ix0 >= 0) & (ix0 < WW - 1) &
                          (iy0 >= 0) & (iy0 < HH - 1) &
                          (iz0 >= 0) & (iz0 < DD - 1);

    if (__all_sync(0xffffffffu, interior)) {
        wAv = 1.0f - fx; wBv = fx;
        wy0 = 1.0f - fy; wy1 = fy;
        wz0 = 1.0f - fz; wz1 = fz;
        xs = ix0; y0c = iy0; y1c = iy0 + 1; z0c = iz0; z1c = iz0 + 1;
    } else {
        const int x1 = ix0 + 1, y1 = iy0 + 1, z1 = iz0 + 1;
        const float wx0 = (ix0 >= 0 && ix0 < WW) ? (1.0f - fx) : 0.0f;
        const float wx1 = (x1  >= 0 && x1  < WW) ? fx          : 0.0f;
        wy0 = (iy0 >= 0 && iy0 < HH) ? (1.0f - fy) : 0.0f;
        wy1 = (y1  >= 0 && y1  < HH) ? fy          : 0.0f;
        wz0 = (iz0 >= 0 && iz0 < DD) ? (1.0f - fz) : 0.0f;
        wz1 = (z1  >= 0 && z1  < DD) ? fz          : 0.0f;
        xs  = min(max(ix0, 0), WW - 1);
        wAv = (ix0 >= 0) ? wx0 : wx1;   // weight for slot's first voxel
        wBv = (ix0 >= 0) ? wx1 : 0.0f;  // weight for slot's second voxel
        y0c = min(max(iy0, 0), HH - 1);
        y1c = min(max(y1,  0), HH - 1);
        z0c = min(max(iz0, 0), DD - 1);
        z1c = min(max(z1,  0), DD - 1);
    }

    const int zb0 = z0c << 14, zb1 = z1c << 14;
    const int yb0 = y0c << 7,  yb1 = y1c << 7;

    const uint4* p = g_scr + ((size_t)b << 21);

    const uint4 g00 = __ldg(p + (zb0 + yb0 + xs));
    const uint4 g01 = __ldg(p + (zb0 + yb1 + xs));
    const uint4 g10 = __ldg(p + (zb1 + yb0 + xs));
    const uint4 g11 = __ldg(p + (zb1 + yb1 + xs));

    const float c00 = wz0 * wy0;
    const float c01 = wz0 * wy1;
    const float c10 = wz1 * wy0;
    const float c11 = wz1 * wy1;

    unsigned long long WA, WB, acc01, acc23;
    PACK_F32X2(WA, wAv, wAv);
    PACK_F32X2(WB, wBv, wBv);
    {
        float zf = 0.0f;
        PACK_F32X2(acc01, zf, zf);
        acc23 = acc01;
    }

    #define COLUMN(g, cwf)                                                     \
    {                                                                          \
        float2 lo01 = __half22float2(*reinterpret_cast<const __half2*>(&g.x)); \
        float2 lo23 = __half22float2(*reinterpret_cast<const __half2*>(&g.y)); \
        float2 hi01 = __half22float2(*reinterpret_cast<const __half2*>(&g.z)); \
        float2 hi23 = __half22float2(*reinterpret_cast<const __half2*>(&g.w)); \
        unsigned long long L01, L23, H01, H23, CW, m0, m1, t01, t23;           \
        PACK_F32X2(L01, lo01.x, lo01.y);                                       \
        PACK_F32X2(L23, lo23.x, lo23.y);                                       \
        PACK_F32X2(H01, hi01.x, hi01.y);                                       \
        PACK_F32X2(H23, hi23.x, hi23.y);                                       \
        PACK_F32X2(CW, cwf, cwf);                                              \
        MUL_F32X2(m0, WB, H01);                                                \
        FMA_F32X2(t01, WA, L01, m0);                                           \
        MUL_F32X2(m1, WB, H23);                                                \
        FMA_F32X2(t23, WA, L23, m1);                                           \
        FMA_F32X2(acc01, CW, t01, acc01);                                      \
        FMA_F32X2(acc23, CW, t23, acc23);                                      \
    }

    COLUMN(g00, c00)
    COLUMN(g01, c01)
    COLUMN(g10, c10)
    COLUMN(g11, c11)

    float r0, r1, r2, r3;
    UNPACK_F32X2(r0, r1, acc01);
    UNPACK_F32X2(r2, r3, acc23);

    const unsigned base = ((unsigned)b << 23) + tid;   // b*C*VOL + tid
    out[base]              = r0;
    out[base + (1u << 21)] = r1;
    out[base + (2u << 21)] = r2;
    out[base + (3u << 21)] = r3;
}

extern "C" void kernel_launch(void* const* d_in, const int* in_sizes, int n_in,
                              void* d_out, int out_size) {
    const float* x       = (const float*)d_in[0];
    const float* im_feat = (const float*)d_in[1];
    const float* pos_w   = (const float*)d_in[2];
    const float* pos_b   = (const float*)d_in[3];
    float* out = (float*)d_out;

    prep_kernel<<<BB * VOL / 4 / 256, 256>>>(x, im_feat, pos_w, pos_b);
    dim3 grid(VOL / 256, BB);
    sample_kernel<<<grid, 256>>>(out);
}